// round 13
// baseline (speedup 1.0000x reference)
#include <cuda_runtime.h>
#include <cuda_bf16.h>
#include <cuda_fp16.h>
#include <math.h>
#include <stdint.h>

// Problem constants
#define B_ 2
#define L_ 2048
#define DIM_ 1024
#define DIN_ 2048
#define NSTATE 16
#define DTR_ 64
#define TOKENS (B_ * L_)   // 4096
#define SPLITK 8
#define NSEG 8
#define SEGLEN (L_ / NSEG)   // 256

// ---------------------------------------------------------------------------
// Scratch buffers (allocation-free: __device__ globals)
// ---------------------------------------------------------------------------
__device__ float g_gate[TOKENS * DIN_];   // silu(res) f32 (scan)
__device__ float g_u[TOKENS * DIN_];      // silu(conv(xs)) exact (scan)
__device__ float g_xdbl[TOKENS * 96];     // u @ W_x exact (scan B/C)
__device__ float g_xdbl_part[SPLITK * TOKENS * 96]; // split-K partials
__device__ float g_delta[TOKENS * DIN_];  // softplus(...)
// segmented-scan intermediates: [b*NSEG+s][d][n]
__device__ float g_segA[B_ * NSEG * DIN_ * NSTATE];
__device__ float g_segH[B_ * NSEG * DIN_ * NSTATE];
__device__ float g_hInit[B_ * NSEG * DIN_ * NSTATE];

// fp16 GEMM operands
__device__ __half g_xh[TOKENS * DIM_];    // fp16 x
__device__ __half g_xsh[TOKENS * DIN_];   // fp16 xs (conv input, from G1)
__device__ __half g_uh[TOKENS * DIN_];    // fp16 u
__device__ __half g_xdh[TOKENS * 96];     // fp16 xdbl
__device__ __half g_yh[TOKENS * DIN_];    // fp16 ys (gated)
// K-major (transposed) fp16 weights
__device__ __half g_win[2 * DIN_ * DIM_]; // [4096][1024]
__device__ __half g_wx[96 * DIN_];        // [96][2048]
__device__ __half g_wdt[DIN_ * DTR_];     // [2048][64]
__device__ __half g_wout[DIM_ * DIN_];    // [1024][2048]

// ---------------------------------------------------------------------------
__device__ __forceinline__ void mma_f16(float* d, const uint32_t* a,
                                        const uint32_t* b) {
    asm volatile(
        "mma.sync.aligned.m16n8k16.row.col.f32.f16.f16.f32 "
        "{%0,%1,%2,%3}, {%4,%5,%6,%7}, {%8,%9}, {%0,%1,%2,%3};"
        : "+f"(d[0]), "+f"(d[1]), "+f"(d[2]), "+f"(d[3])
        : "r"(a[0]), "r"(a[1]), "r"(a[2]), "r"(a[3]),
          "r"(b[0]), "r"(b[1]));
}

__device__ __forceinline__ void ldsm_x4(uint32_t& r0, uint32_t& r1,
                                        uint32_t& r2, uint32_t& r3,
                                        uint32_t addr) {
    asm volatile(
        "ldmatrix.sync.aligned.m8n8.x4.shared.b16 {%0,%1,%2,%3}, [%4];"
        : "=r"(r0), "=r"(r1), "=r"(r2), "=r"(r3) : "r"(addr));
}

__device__ __forceinline__ void cp16(uint32_t daddr, const void* src, int zfill) {
    asm volatile("cp.async.cg.shared.global [%0], [%1], 16, %2;"
                 :: "r"(daddr), "l"(src), "r"(zfill) : "memory");
}
__device__ __forceinline__ void cp_commit() {
    asm volatile("cp.async.commit_group;" ::: "memory");
}
__device__ __forceinline__ void cp_wait1() {
    asm volatile("cp.async.wait_group 1;" ::: "memory");
}

// ---------------------------------------------------------------------------
// f32 -> fp16 elementwise
// ---------------------------------------------------------------------------
__global__ void to_f16(const float* __restrict__ in,
                       __half* __restrict__ out, int n)
{
    const int idx = blockIdx.x * blockDim.x + threadIdx.x;
    if (idx < n) out[idx] = __float2half_rn(in[idx]);
}

// ---------------------------------------------------------------------------
// Weight transpose + fp16: out[C][R] = f16(in[R][C])
// ---------------------------------------------------------------------------
__global__ void transpose_f16(const float* __restrict__ in,
                              __half* __restrict__ out, int R, int C)
{
    __shared__ float t[32][33];
    const int bx = blockIdx.x * 32, by = blockIdx.y * 32;
    const int x = threadIdx.x, y0 = threadIdx.y;
#pragma unroll
    for (int i = 0; i < 32; i += 8)
        t[y0 + i][x] = in[(size_t)(by + y0 + i) * C + bx + x];
    __syncthreads();
#pragma unroll
    for (int i = 0; i < 32; i += 8)
        out[(size_t)(bx + y0 + i) * R + by + x] =
            __float2half_rn(t[x][y0 + i]);
}

// ---------------------------------------------------------------------------
// Deterministic split-K reduction: xdbl = sum_z part[z]; plus fp16 copy
// ---------------------------------------------------------------------------
__global__ void reduce_splitk(const float* __restrict__ part,
                              float* __restrict__ out,
                              __half* __restrict__ outh)
{
    const int idx = blockIdx.x * blockDim.x + threadIdx.x;
    if (idx >= TOKENS * 96) return;
    float s = 0.f;
#pragma unroll
    for (int z = 0; z < SPLITK; z++)
        s += part[(size_t)z * TOKENS * 96 + idx];
    out[idx] = s;
    outh[idx] = __float2half_rn(s);
}

// ---------------------------------------------------------------------------
// WIDE fp16 GEMM: BM=128, BN=256, BK=64, 256 threads, warp tile 64x64.
//   1 CTA/SM, 3-stage cp.async pipeline, ldmatrix fragments.
// EPI: 0 plain f32 store, 1 split (xs fp16 -> H0 / silu f32 -> C1)
// ---------------------------------------------------------------------------
template <int EPI>
__global__ void __launch_bounds__(256, 1)
gemm_wide(const __half* __restrict__ A, int lda,
          const __half* __restrict__ Bt, int ldb,
          int K,
          float* __restrict__ C0, float* __restrict__ C1,
          __half* __restrict__ H0, int ldc)
{
    constexpr int BM = 128, BN = 256;
    constexpr int PADW = 36;                   // words per 64-elem row + pad
    constexpr int ACOMP = BM * PADW;           // 4608 words
    constexpr int BCOMP = BN * PADW;           // 9216 words
    constexpr int BUFW = ACOMP + BCOMP;        // per stage

    extern __shared__ __align__(16) uint32_t dynsmem[];
    const uint32_t s_addr = (uint32_t)__cvta_generic_to_shared(dynsmem);

    const int tid = threadIdx.x;
    const int wid = tid >> 5;
    const int lane = tid & 31;
    const int gr = lane >> 2;
    const int tig = lane & 3;
    const int warp_m = wid >> 2;  // 0..1 -> rows warp_m*64
    const int warp_n = wid & 3;   // 0..3 -> cols warp_n*64

    const int block_row = blockIdx.y * BM;
    const int block_col = blockIdx.x * BN;

    const int KT = K >> 6;

    const __half* Ag = A + (size_t)block_row * lda;
    const __half* Bg = Bt + (size_t)block_col * ldb;

    float acc[4][8][4];
#pragma unroll
    for (int i = 0; i < 4; i++)
#pragma unroll
        for (int j = 0; j < 8; j++)
#pragma unroll
            for (int e = 0; e < 4; e++) acc[i][j][e] = 0.f;

    const int rowA = (lane & 7) + ((lane >> 3) & 1) * 8;
    const int kAb  = ((lane >> 4) & 1) * 16;
    const int rowB = (lane & 7) + ((lane >> 4) & 1) * 8;
    const int kBb  = ((lane >> 3) & 1) * 16;

    auto stage = [&](int kt, int slot) {
        const int kcol = kt << 6;
        const uint32_t base = s_addr + (uint32_t)slot * BUFW * 4;
#pragma unroll
        for (int i = 0; i < 4; i++) {          // A: 128 rows x 8 segs
            const int l = tid + (i << 8);
            const int r = l >> 3, seg = l & 7;
            cp16(base + (uint32_t)(r * PADW * 4 + seg * 16),
                 Ag + (size_t)r * lda + kcol + seg * 8, 16);
        }
#pragma unroll
        for (int i = 0; i < 8; i++) {          // B: 256 rows x 8 segs
            const int l = tid + (i << 8);
            const int r = l >> 3, seg = l & 7;
            cp16(base + ACOMP * 4 + (uint32_t)(r * PADW * 4 + seg * 16),
                 Bg + (size_t)r * ldb + kcol + seg * 8, 16);
        }
        cp_commit();
    };

    stage(0, 0);
    if (KT > 1) stage(1, 1); else cp_commit();
    cp_wait1();
    __syncthreads();

    for (int kt = 0; kt < KT; kt++) {
        const int slot = kt % 3;
        if (kt + 2 < KT) stage(kt + 2, (kt + 2) % 3);
        else cp_commit();

        const uint32_t abase = s_addr + (uint32_t)slot * BUFW * 4
                             + (uint32_t)((warp_m * 64 + rowA) * PADW * 4 + kAb);
        const uint32_t bbase = s_addr + (uint32_t)(slot * BUFW + ACOMP) * 4
                             + (uint32_t)((warp_n * 64 + rowB) * PADW * 4 + kBb);

#pragma unroll
        for (int ks = 0; ks < 4; ks++) {
            const uint32_t koff = ks * 32;
            uint32_t a[4][4];
#pragma unroll
            for (int im = 0; im < 4; im++)
                ldsm_x4(a[im][0], a[im][1], a[im][2], a[im][3],
                        abase + im * (16 * PADW * 4) + koff);
            uint32_t bb[4][4];
#pragma unroll
            for (int p = 0; p < 4; p++)
                ldsm_x4(bb[p][0], bb[p][1], bb[p][2], bb[p][3],
                        bbase + p * (16 * PADW * 4) + koff);
#pragma unroll
            for (int im = 0; im < 4; im++)
#pragma unroll
                for (int in = 0; in < 8; in++)
                    mma_f16(acc[im][in], a[im], &bb[in >> 1][(in & 1) * 2]);
        }

        cp_wait1();
        __syncthreads();
    }

    // --- epilogue ---
#pragma unroll
    for (int im = 0; im < 4; im++) {
        const int r0 = block_row + warp_m * 64 + im * 16 + gr;
#pragma unroll
        for (int in = 0; in < 8; in++) {
            const int c0 = block_col + warp_n * 64 + in * 8 + 2 * tig;
#pragma unroll
            for (int half = 0; half < 2; half++) {
                const int r = r0 + half * 8;
                const float v0 = acc[im][in][2 * half];
                const float v1 = acc[im][in][2 * half + 1];
                if (EPI == 0) {
                    *reinterpret_cast<float2*>(&C0[(size_t)r * ldc + c0]) =
                        make_float2(v0, v1);
                } else { // EPI == 1
                    if (block_col < DIN_) {
                        *reinterpret_cast<__half2*>(&H0[(size_t)r * DIN_ + c0]) =
                            __floats2half2_rn(v0, v1);
                    } else {
                        const float s0 = v0 / (1.f + __expf(-v0));
                        const float s1 = v1 / (1.f + __expf(-v1));
                        *reinterpret_cast<float2*>(
                            &C1[(size_t)r * DIN_ + (c0 - DIN_)]) =
                            make_float2(s0, s1);
                    }
                }
            }
        }
    }
}

// ---------------------------------------------------------------------------
// Narrow fp16 GEMM (BM=BN=128, BK=64) — used for G3 (split-K) and G4.
// EPI: 2 bias+softplus, 3 split-K partial store with N guard
// ---------------------------------------------------------------------------
template <int EPI>
__global__ void __launch_bounds__(256, 2)
gemm_f16(const __half* __restrict__ A, int lda,
         const __half* __restrict__ Bt, int ldb,
         int N, int K,
         const float* __restrict__ bias,
         float* __restrict__ C0, int ldc)
{
    constexpr int BM = 128, BN = 128;
    constexpr int PADW = 36;
    constexpr int COMP = BM * PADW;
    constexpr int BUFW = 2 * COMP;
    constexpr bool NG = (EPI == 3);

    extern __shared__ __align__(16) uint32_t dynsmem[];
    const uint32_t s_addr = (uint32_t)__cvta_generic_to_shared(dynsmem);

    const int tid = threadIdx.x;
    const int wid = tid >> 5;
    const int lane = tid & 31;
    const int gr = lane >> 2;
    const int tig = lane & 3;
    const int warp_m = wid >> 2;
    const int warp_n = wid & 3;

    const int block_row = blockIdx.y * BM;
    const int block_col = blockIdx.x * BN;

    const int KT_total = K >> 6;
    const int kt_per = KT_total / gridDim.z;
    const int kt0 = blockIdx.z * kt_per;
    const int kt_end = kt0 + kt_per;

    const __half* Ag = A + (size_t)block_row * lda;
    const __half* Bg = Bt + (size_t)block_col * ldb;

    float acc[4][4][4];
#pragma unroll
    for (int i = 0; i < 4; i++)
#pragma unroll
        for (int j = 0; j < 4; j++)
#pragma unroll
            for (int e = 0; e < 4; e++) acc[i][j][e] = 0.f;

    const int rowA = (lane & 7) + ((lane >> 3) & 1) * 8;
    const int kAb  = ((lane >> 4) & 1) * 16;
    const int rowB = (lane & 7) + ((lane >> 4) & 1) * 8;
    const int kBb  = ((lane >> 3) & 1) * 16;

    auto stage = [&](int kt, int slot) {
        const int kcol = kt << 6;
        const uint32_t base = s_addr + (uint32_t)slot * BUFW * 4;
#pragma unroll
        for (int i = 0; i < 4; i++) {
            const int l = tid + (i << 8);
            const int r = l >> 3, seg = l & 7;
            const uint32_t doff = (uint32_t)(r * PADW * 4 + seg * 16);
            cp16(base + doff, Ag + (size_t)r * lda + kcol + seg * 8, 16);
            int zf = 16, rs = r;
            if (NG && block_col + r >= N) { zf = 0; rs = 0; }
            cp16(base + COMP * 4 + doff,
                 Bg + (size_t)rs * ldb + kcol + seg * 8, zf);
        }
        cp_commit();
    };

    stage(kt0, 0);
    if (kt0 + 1 < kt_end) stage(kt0 + 1, 1); else cp_commit();
    cp_wait1();
    __syncthreads();

    for (int kt = kt0; kt < kt_end; kt++) {
        const int slot = (kt - kt0) % 3;
        if (kt + 2 < kt_end) stage(kt + 2, (kt + 2 - kt0) % 3);
        else cp_commit();

        const uint32_t abase = s_addr + (uint32_t)slot * BUFW * 4
                             + (uint32_t)((warp_m * 64 + rowA) * PADW * 4 + kAb);
        const uint32_t bbase = s_addr + (uint32_t)(slot * BUFW + COMP) * 4
                             + (uint32_t)((warp_n * 32 + rowB) * PADW * 4 + kBb);

#pragma unroll
        for (int ks = 0; ks < 4; ks++) {
            const uint32_t koff = ks * 32;
            uint32_t a[4][4];
#pragma unroll
            for (int im = 0; im < 4; im++)
                ldsm_x4(a[im][0], a[im][1], a[im][2], a[im][3],
                        abase + im * (16 * PADW * 4) + koff);
            uint32_t bb[2][4];
#pragma unroll
            for (int p = 0; p < 2; p++)
                ldsm_x4(bb[p][0], bb[p][1], bb[p][2], bb[p][3],
                        bbase + p * (16 * PADW * 4) + koff);
#pragma unroll
            for (int im = 0; im < 4; im++)
#pragma unroll
                for (int in = 0; in < 4; in++)
                    mma_f16(acc[im][in], a[im], &bb[in >> 1][(in & 1) * 2]);
        }

        cp_wait1();
        __syncthreads();
    }

    float* C0z = C0;
    if (EPI == 3)
        C0z = C0 + (size_t)blockIdx.z * TOKENS * 96;

#pragma unroll
    for (int im = 0; im < 4; im++) {
        const int r0 = block_row + warp_m * 64 + im * 16 + gr;
#pragma unroll
        for (int in = 0; in < 4; in++) {
            const int c0 = block_col + warp_n * 32 + in * 8 + 2 * tig;
#pragma unroll
            for (int half = 0; half < 2; half++) {
                const int r = r0 + half * 8;
                const float v0 = acc[im][in][2 * half];
                const float v1 = acc[im][in][2 * half + 1];
                if (EPI == 2) {
                    const float t0 = v0 + __ldg(&bias[c0]);
                    const float t1 = v1 + __ldg(&bias[c0 + 1]);
                    const float s0 = (t0 > 20.f) ? t0 : log1pf(__expf(t0));
                    const float s1 = (t1 > 20.f) ? t1 : log1pf(__expf(t1));
                    *reinterpret_cast<float2*>(&C0[(size_t)r * ldc + c0]) =
                        make_float2(s0, s1);
                } else { // EPI == 3
                    if (c0 + 1 < N) {
                        *reinterpret_cast<float2*>(&C0z[(size_t)r * ldc + c0]) =
                            make_float2(v0, v1);
                    } else if (c0 < N) {
                        C0z[(size_t)r * ldc + c0] = v0;
                    }
                }
            }
        }
    }
}

// ---------------------------------------------------------------------------
// Depthwise causal conv1d (k=4) + bias + SiLU; 8 channels/thread, fp16 input
// ---------------------------------------------------------------------------
__global__ void conv_silu_kernel(const __half* __restrict__ xs,
                                 const float* __restrict__ w,
                                 const float* __restrict__ bias,
                                 float* __restrict__ u,
                                 __half* __restrict__ uh)
{
    const int idx = blockIdx.x * blockDim.x + threadIdx.x;
    const int t = idx >> 8;
    const int c0 = (idx & 255) << 3;
    const int l = t & (L_ - 1);
    const int tbase = t - l;

    float acc[8];
    {
        const float4 b0 = *reinterpret_cast<const float4*>(&bias[c0]);
        const float4 b1 = *reinterpret_cast<const float4*>(&bias[c0 + 4]);
        acc[0] = b0.x; acc[1] = b0.y; acc[2] = b0.z; acc[3] = b0.w;
        acc[4] = b1.x; acc[5] = b1.y; acc[6] = b1.z; acc[7] = b1.w;
    }
    float wv[8][4];
#pragma unroll
    for (int j = 0; j < 8; j++) {
        const float4 w4 = *reinterpret_cast<const float4*>(&w[(c0 + j) * 4]);
        wv[j][0] = w4.x; wv[j][1] = w4.y; wv[j][2] = w4.z; wv[j][3] = w4.w;
    }

#pragma unroll
    for (int k = 0; k < 4; k++) {
        const int lp = l - 3 + k;
        if (lp >= 0) {
            const uint4 hv = *reinterpret_cast<const uint4*>(
                xs + ((size_t)(tbase + lp) * DIN_ + c0));
            const __half2* h2 = reinterpret_cast<const __half2*>(&hv);
#pragma unroll
            for (int p = 0; p < 4; p++) {
                const float2 f = __half22float2(h2[p]);
                acc[2 * p]     = fmaf(f.x, wv[2 * p][k],     acc[2 * p]);
                acc[2 * p + 1] = fmaf(f.y, wv[2 * p + 1][k], acc[2 * p + 1]);
            }
        }
    }

    float s[8];
#pragma unroll
    for (int j = 0; j < 8; j++)
        s[j] = acc[j] / (1.f + __expf(-acc[j]));

    float* up = u + (size_t)t * DIN_ + c0;
    *reinterpret_cast<float4*>(up)     = make_float4(s[0], s[1], s[2], s[3]);
    *reinterpret_cast<float4*>(up + 4) = make_float4(s[4], s[5], s[6], s[7]);
    __half2 hs[4];
#pragma unroll
    for (int p = 0; p < 4; p++)
        hs[p] = __floats2half2_rn(s[2 * p], s[2 * p + 1]);
    *reinterpret_cast<uint4*>(uh + (size_t)t * DIN_ + c0) =
        *reinterpret_cast<uint4*>(hs);
}

// ---------------------------------------------------------------------------
// Segmented scan pass 1: per (b, seg, d, n) compute (prod dA, local h end)
// ---------------------------------------------------------------------------
__global__ void scan_pass1(const float* __restrict__ delta,
                           const float* __restrict__ u,
                           const float* __restrict__ xdbl,
                           const float* __restrict__ A_log,
                           float* __restrict__ segA,
                           float* __restrict__ segH)
{
    constexpr int CH = 64;
    __shared__ float sD[CH][16];
    __shared__ float sU[CH][16];
    __shared__ float sB[CH][16];

    const int bs = blockIdx.y;
    const int b = bs >> 3;
    const int seg = bs & 7;
    const int dbase = blockIdx.x * 16;
    const int tid = threadIdx.x;
    const int warp = tid >> 5;
    const int lane = tid & 31;
    const int half = lane >> 4;
    const int n = lane & 15;
    const int dl = (warp << 1) + half;
    const int d = dbase + dl;

    const float cA = -__expf(A_log[d * NSTATE + n]) * 1.44269504f;

    const int li = tid & 15;
    const int lrow = tid >> 4;
    const int l0 = seg * SEGLEN;

    float h = 0.f, aP = 1.f;

    for (int c0 = 0; c0 < SEGLEN; c0 += CH) {
#pragma unroll
        for (int p = 0; p < CH / 16; p++) {
            const int l = l0 + c0 + p * 16 + lrow;
            const size_t t = (size_t)b * L_ + l;
            sD[p * 16 + lrow][li] = delta[t * DIN_ + dbase + li];
            sU[p * 16 + lrow][li] = u[t * DIN_ + dbase + li];
            sB[p * 16 + lrow][li] = xdbl[t * 96 + 64 + li];
        }
        __syncthreads();

        for (int i = 0; i < CH; i++) {
            const float dlt = sD[i][dl];
            const float uu  = sU[i][dl];
            const float bb  = sB[i][n];
            const float dA  = exp2f(dlt * cA);
            h = fmaf(dA, h, dlt * bb * uu);
            aP *= dA;
        }
        __syncthreads();
    }

    const size_t o = ((size_t)bs * DIN_ + d) * NSTATE + n;
    segA[o] = aP;
    segH[o] = h;
}

// ---------------------------------------------------------------------------
// Segment combine: serial prefix over NSEG per chain -> h_init per segment
// ---------------------------------------------------------------------------
__global__ void scan_combine(const float* __restrict__ segA,
                             const float* __restrict__ segH,
                             float* __restrict__ hInit)
{
    const int idx = blockIdx.x * blockDim.x + threadIdx.x;
    if (idx >= B_ * DIN_ * NSTATE) return;
    const int b = idx / (DIN_ * NSTATE);
    const int rem = idx - b * (DIN_ * NSTATE);
    float h = 0.f;
#pragma unroll
    for (int s = 0; s < NSEG; s++) {
        const size_t o = ((size_t)(b * NSEG + s) * DIN_) * NSTATE + rem;
        hInit[o] = h;
        h = segA[o] * h + segH[o];
    }
}

// ---------------------------------------------------------------------------
// Segmented scan pass 2: recompute recurrence from h_init, emit gated output
// ---------------------------------------------------------------------------
__global__ void scan_pass2(const float* __restrict__ delta,
                           const float* __restrict__ u,
                           const float* __restrict__ xdbl,
                           const float* __restrict__ gate,
                           const float* __restrict__ A_log,
                           const float* __restrict__ Dv,
                           const float* __restrict__ hInit,
                           __half* __restrict__ yh)
{
    constexpr int CH = 64;
    __shared__ float sD[CH][16];
    __shared__ float sU[CH][16];
    __shared__ float sG[CH][16];
    __shared__ float sB[CH][16];
    __shared__ float sC[CH][16];
    __shared__ float sY[CH][16];

    const int bs = blockIdx.y;
    const int b = bs >> 3;
    const int seg = bs & 7;
    const int dbase = blockIdx.x * 16;
    const int tid = threadIdx.x;
    const int warp = tid >> 5;
    const int lane = tid & 31;
    const int half = lane >> 4;
    const int n = lane & 15;
    const int dl = (warp << 1) + half;
    const int d = dbase + dl;

    const float cA = -__expf(A_log[d * NSTATE + n]) * 1.44269504f;
    const float Dd = Dv[d];

    const int li = tid & 15;
    const int lrow = tid >> 4;
    const int l0 = seg * SEGLEN;

    float h = hInit[((size_t)bs * DIN_ + d) * NSTATE + n];

    for (int c0 = 0; c0 < SEGLEN; c0 += CH) {
#pragma unroll
        for (int p = 0; p < CH / 16; p++) {
            const int l = l0 + c0 + p * 16 + lrow;
            const size_t t = (size_t)b * L_ + l;
            sD[p * 16 + lrow][li] = delta[t * DIN_ + dbase + li];
            sU[p * 16 + lrow][li] = u[t * DIN_ + dbase + li];
            sG[p * 16 + lrow][li] = gate[t * DIN_ + dbase + li];
            sB[p * 16 + lrow][li] = xdbl[t * 96 + 64 + li];
            sC[p * 16 + lrow][li] = xdbl[t * 96 + 80 + li];
        }
        __syncthreads();

        for (int i = 0; i < CH; i++) {
            const float dlt = sD[i][dl];
            const float uu  = sU[i][dl];
            const float bb  = sB[i][n];
            const float cc  = sC[i][n];
            const float dA  = exp2f(dlt * cA);
            h = fmaf(dA, h, dlt * bb * uu);
            float py = h * cc;
            py += __shfl_xor_sync(0xffffffffu, py, 1);
            py += __shfl_xor_sync(0xffffffffu, py, 2);
            py += __shfl_xor_sync(0xffffffffu, py, 4);
            py += __shfl_xor_sync(0xffffffffu, py, 8);
            if (n == 0)
                sY[i][dl] = (py + uu * Dd) * sG[i][dl];
        }
        __syncthreads();

#pragma unroll
        for (int p = 0; p < CH / 16; p++) {
            const int l = l0 + c0 + p * 16 + lrow;
            yh[((size_t)b * L_ + l) * DIN_ + dbase + li] =
                __float2half_rn(sY[p * 16 + lrow][li]);
        }
        __syncthreads();
    }
}

// ---------------------------------------------------------------------------
extern "C" void kernel_launch(void* const* d_in, const int* in_sizes, int n_in,
                              void* d_out, int out_size)
{
    const float* x      = (const float*)d_in[0];
    const float* W_in   = (const float*)d_in[1];
    const float* conv_w = (const float*)d_in[2];
    const float* conv_b = (const float*)d_in[3];
    const float* W_x    = (const float*)d_in[4];
    const float* W_dt   = (const float*)d_in[5];
    const float* b_dt   = (const float*)d_in[6];
    const float* W_out  = (const float*)d_in[7];
    const float* A_log  = (const float*)d_in[8];
    const float* Dv     = (const float*)d_in[9];
    float* out = (float*)d_out;

    float *gate, *u, *xdbl, *xdbl_part, *delta, *segA, *segH, *hInit;
    __half *xh, *xsh, *uh, *xdh, *yh, *win, *wx, *wdt, *wout;
    cudaGetSymbolAddress((void**)&gate,      g_gate);
    cudaGetSymbolAddress((void**)&u,         g_u);
    cudaGetSymbolAddress((void**)&xdbl,      g_xdbl);
    cudaGetSymbolAddress((void**)&xdbl_part, g_xdbl_part);
    cudaGetSymbolAddress((void**)&delta,     g_delta);
    cudaGetSymbolAddress((void**)&segA,      g_segA);
    cudaGetSymbolAddress((void**)&segH,      g_segH);
    cudaGetSymbolAddress((void**)&hInit,     g_hInit);
    cudaGetSymbolAddress((void**)&xh,        g_xh);
    cudaGetSymbolAddress((void**)&xsh,       g_xsh);
    cudaGetSymbolAddress((void**)&uh,        g_uh);
    cudaGetSymbolAddress((void**)&xdh,       g_xdh);
    cudaGetSymbolAddress((void**)&yh,        g_yh);
    cudaGetSymbolAddress((void**)&win,       g_win);
    cudaGetSymbolAddress((void**)&wx,        g_wx);
    cudaGetSymbolAddress((void**)&wdt,       g_wdt);
    cudaGetSymbolAddress((void**)&wout,      g_wout);

    constexpr int SMEM_N = 3 * 2 * 128 * 36 * 4;           // 110592 (narrow)
    constexpr int SMEM_W = 3 * (128 + 256) * 36 * 4;       // 165888 (wide)
    cudaFuncSetAttribute(gemm_wide<0>, cudaFuncAttributeMaxDynamicSharedMemorySize, SMEM_W);
    cudaFuncSetAttribute(gemm_wide<1>, cudaFuncAttributeMaxDynamicSharedMemorySize, SMEM_W);
    cudaFuncSetAttribute(gemm_f16<2>,  cudaFuncAttributeMaxDynamicSharedMemorySize, SMEM_N);
    cudaFuncSetAttribute(gemm_f16<3>,  cudaFuncAttributeMaxDynamicSharedMemorySize, SMEM_N);

    // Convert x; transpose W_in; (G1 placed early so ncu -s lands on it)
    to_f16<<<(TOKENS * DIM_ + 255) / 256, 256>>>(x, xh, TOKENS * DIM_);
    transpose_f16<<<dim3(2 * DIN_ / 32, DIM_ / 32), dim3(32, 8)>>>(W_in, win, DIM_, 2 * DIN_);
    transpose_f16<<<dim3(96 / 32, DIN_ / 32), dim3(32, 8)>>>(W_x, wx, DIN_, 96);

    // G1: x @ W_in -> xs (fp16) / silu(res) (f32 gate)   [wide tile]
    gemm_wide<1><<<dim3(2 * DIN_ / 256, TOKENS / 128), 256, SMEM_W>>>(
        xh, DIM_, win, DIM_, DIM_, nullptr, gate, xsh, 0);

    transpose_f16<<<dim3(DIN_ / 32, DTR_ / 32), dim3(32, 8)>>>(W_dt, wdt, DTR_, DIN_);
    transpose_f16<<<dim3(DIM_ / 32, DIN_ / 32), dim3(32, 8)>>>(W_out, wout, DIN_, DIM_);

    // Depthwise causal conv + SiLU -> u (f32) + uh (fp16)
    conv_silu_kernel<<<TOKENS, 256>>>(xsh, conv_w, conv_b, u, uh);

    // G3: x_dbl = u @ W_x (N=96), deterministic split-K=8 [narrow]
    gemm_f16<3><<<dim3(1, TOKENS / 128, SPLITK), 256, SMEM_N>>>(
        uh, DIN_, wx, DIN_, 96, DIN_, nullptr, xdbl_part, 96);
    reduce_splitk<<<(TOKENS * 96 + 255) / 256, 256>>>(xdbl_part, xdbl, xdh);

    // G4: delta = softplus(x_dbl[:, :64] @ W_dt + b_dt)  [narrow]
    gemm_f16<2><<<dim3(DIN_ / 128, TOKENS / 128, 1), 256, SMEM_N>>>(
        xdh, 96, wdt, DTR_, DIN_, DTR_, b_dt, delta, DIN_);

    // Segmented selective scan: pass1 -> combine -> pass2
    scan_pass1<<<dim3(DIN_ / 16, B_ * NSEG), 256>>>(
        delta, u, xdbl, A_log, segA, segH);
    scan_combine<<<(B_ * DIN_ * NSTATE + 255) / 256, 256>>>(
        segA, segH, hInit);
    scan_pass2<<<dim3(DIN_ / 16, B_ * NSEG), 256>>>(
        delta, u, xdbl, gate, A_log, Dv, hInit, yh);

    // G6: out = ys @ W_out   [wide tile]
    gemm_wide<0><<<dim3(DIM_ / 256, TOKENS / 128), 256, SMEM_W>>>(
        yh, DIN_, wout, DIN_, DIN_, out, nullptr, nullptr, DIM_);
}

// round 15
// speedup vs baseline: 1.0617x; 1.0617x over previous
#include <cuda_runtime.h>
#include <cuda_bf16.h>
#include <cuda_fp16.h>
#include <math.h>
#include <stdint.h>

// Problem constants
#define B_ 2
#define L_ 2048
#define DIM_ 1024
#define DIN_ 2048
#define NSTATE 16
#define DTR_ 64
#define TOKENS (B_ * L_)   // 4096
#define SPLITK 8
#define NSEG 8
#define SEGLEN (L_ / NSEG)   // 256

// ---------------------------------------------------------------------------
// Scratch buffers (allocation-free: __device__ globals)
// ---------------------------------------------------------------------------
__device__ float g_xdbl[TOKENS * 96];     // u @ W_x exact (scan B/C)
__device__ float g_xdbl_part[SPLITK * TOKENS * 96]; // split-K partials
__device__ float g_delta[TOKENS * DIN_];  // softplus(...)
// segmented-scan intermediates: [b*NSEG+s][d][n]
__device__ float g_segA[B_ * NSEG * DIN_ * NSTATE];
__device__ float g_segH[B_ * NSEG * DIN_ * NSTATE];
__device__ float g_hInit[B_ * NSEG * DIN_ * NSTATE];

// fp16 operands
__device__ __half g_xh[TOKENS * DIM_];    // fp16 x
__device__ __half g_xsh[TOKENS * DIN_];   // fp16 xs (conv input, from G1)
__device__ __half g_gateh[TOKENS * DIN_]; // fp16 silu(res)
__device__ __half g_uh[TOKENS * DIN_];    // fp16 u
__device__ __half g_xdh[TOKENS * 96];     // fp16 xdbl
__device__ __half g_yh[TOKENS * DIN_];    // fp16 ys (gated)
// K-major (transposed) fp16 weights
__device__ __half g_win[2 * DIN_ * DIM_]; // [4096][1024]
__device__ __half g_wx[96 * DIN_];        // [96][2048]
__device__ __half g_wdt[DIN_ * DTR_];     // [2048][64]
__device__ __half g_wout[DIM_ * DIN_];    // [1024][2048]

// ---------------------------------------------------------------------------
__device__ __forceinline__ void mma_f16(float* d, const uint32_t* a,
                                        const uint32_t* b) {
    asm volatile(
        "mma.sync.aligned.m16n8k16.row.col.f32.f16.f16.f32 "
        "{%0,%1,%2,%3}, {%4,%5,%6,%7}, {%8,%9}, {%0,%1,%2,%3};"
        : "+f"(d[0]), "+f"(d[1]), "+f"(d[2]), "+f"(d[3])
        : "r"(a[0]), "r"(a[1]), "r"(a[2]), "r"(a[3]),
          "r"(b[0]), "r"(b[1]));
}

__device__ __forceinline__ void ldsm_x4(uint32_t& r0, uint32_t& r1,
                                        uint32_t& r2, uint32_t& r3,
                                        uint32_t addr) {
    asm volatile(
        "ldmatrix.sync.aligned.m8n8.x4.shared.b16 {%0,%1,%2,%3}, [%4];"
        : "=r"(r0), "=r"(r1), "=r"(r2), "=r"(r3) : "r"(addr));
}

__device__ __forceinline__ void cp16(uint32_t daddr, const void* src, int zfill) {
    asm volatile("cp.async.cg.shared.global [%0], [%1], 16, %2;"
                 :: "r"(daddr), "l"(src), "r"(zfill) : "memory");
}
__device__ __forceinline__ void cp_commit() {
    asm volatile("cp.async.commit_group;" ::: "memory");
}
__device__ __forceinline__ void cp_wait1() {
    asm volatile("cp.async.wait_group 1;" ::: "memory");
}

// ---------------------------------------------------------------------------
// f32 -> fp16 elementwise
// ---------------------------------------------------------------------------
__global__ void to_f16(const float* __restrict__ in,
                       __half* __restrict__ out, int n)
{
    const int idx = blockIdx.x * blockDim.x + threadIdx.x;
    if (idx < n) out[idx] = __float2half_rn(in[idx]);
}

// ---------------------------------------------------------------------------
// Weight transpose + fp16: out[C][R] = f16(in[R][C])
// ---------------------------------------------------------------------------
__global__ void transpose_f16(const float* __restrict__ in,
                              __half* __restrict__ out, int R, int C)
{
    __shared__ float t[32][33];
    const int bx = blockIdx.x * 32, by = blockIdx.y * 32;
    const int x = threadIdx.x, y0 = threadIdx.y;
#pragma unroll
    for (int i = 0; i < 32; i += 8)
        t[y0 + i][x] = in[(size_t)(by + y0 + i) * C + bx + x];
    __syncthreads();
#pragma unroll
    for (int i = 0; i < 32; i += 8)
        out[(size_t)(bx + y0 + i) * R + by + x] =
            __float2half_rn(t[x][y0 + i]);
}

// ---------------------------------------------------------------------------
// Deterministic split-K reduction: xdbl = sum_z part[z]; plus fp16 copy
// ---------------------------------------------------------------------------
__global__ void reduce_splitk(const float* __restrict__ part,
                              float* __restrict__ out,
                              __half* __restrict__ outh)
{
    const int idx = blockIdx.x * blockDim.x + threadIdx.x;
    if (idx >= TOKENS * 96) return;
    float s = 0.f;
#pragma unroll
    for (int z = 0; z < SPLITK; z++)
        s += part[(size_t)z * TOKENS * 96 + idx];
    out[idx] = s;
    outh[idx] = __float2half_rn(s);
}

// ---------------------------------------------------------------------------
// fp16 GEMM: C[M,N] = A[M,K] @ Bt[N,K]^T (f32 accumulate)
//   BM=BN=128, BK=64, 256 threads (2x4 warps, warp tile 64x32), 2 CTAs/SM.
//   ldmatrix fragment loads, 3-stage cp.async pipeline (wait_group 1).
// EPI: 0 plain f32 store, 1 split (xs fp16 -> H0 / silu fp16 -> H1),
//      2 bias+softplus -> C0, 3 split-K partial store with N guard
// ---------------------------------------------------------------------------
template <int EPI>
__global__ void __launch_bounds__(256, 2)
gemm_f16(const __half* __restrict__ A, int lda,
         const __half* __restrict__ Bt, int ldb,
         int N, int K,
         const float* __restrict__ bias,
         float* __restrict__ C0,
         __half* __restrict__ H0, __half* __restrict__ H1, int ldc)
{
    constexpr int BM = 128, BN = 128;
    constexpr int PADW = 36;                  // words per row (32 data + 4 pad)
    constexpr int COMP = BM * PADW;           // 4608 words per tile
    constexpr int BUFW = 2 * COMP;            // A + B per stage
    constexpr bool NG = (EPI == 3);

    extern __shared__ __align__(16) uint32_t dynsmem[];
    const uint32_t s_addr = (uint32_t)__cvta_generic_to_shared(dynsmem);

    const int tid = threadIdx.x;
    const int wid = tid >> 5;
    const int lane = tid & 31;
    const int gr = lane >> 2;
    const int tig = lane & 3;
    const int warp_m = wid >> 2;  // 0..1 -> rows warp_m*64
    const int warp_n = wid & 3;   // 0..3 -> cols warp_n*32

    const int block_row = blockIdx.y * BM;
    const int block_col = blockIdx.x * BN;

    const int KT_total = K >> 6;
    const int kt_per = KT_total / gridDim.z;
    const int kt0 = blockIdx.z * kt_per;
    const int kt_end = kt0 + kt_per;

    const __half* Ag = A + (size_t)block_row * lda;
    const __half* Bg = Bt + (size_t)block_col * ldb;

    float acc[4][4][4];
#pragma unroll
    for (int i = 0; i < 4; i++)
#pragma unroll
        for (int j = 0; j < 4; j++)
#pragma unroll
            for (int e = 0; e < 4; e++) acc[i][j][e] = 0.f;

    const int rowA = (lane & 7) + ((lane >> 3) & 1) * 8;
    const int kAb  = ((lane >> 4) & 1) * 16;
    const int rowB = (lane & 7) + ((lane >> 4) & 1) * 8;
    const int kBb  = ((lane >> 3) & 1) * 16;

    auto stage = [&](int kt, int slot) {
        const int kcol = kt << 6;
        const uint32_t base = s_addr + (uint32_t)slot * BUFW * 4;
#pragma unroll
        for (int i = 0; i < 4; i++) {
            const int l = tid + (i << 8);
            const int r = l >> 3, seg = l & 7;
            const uint32_t doff = (uint32_t)(r * PADW * 4 + seg * 16);
            cp16(base + doff, Ag + (size_t)r * lda + kcol + seg * 8, 16);
            int zf = 16, rs = r;
            if (NG && block_col + r >= N) { zf = 0; rs = 0; }
            cp16(base + COMP * 4 + doff,
                 Bg + (size_t)rs * ldb + kcol + seg * 8, zf);
        }
        cp_commit();
    };

    stage(kt0, 0);
    if (kt0 + 1 < kt_end) stage(kt0 + 1, 1); else cp_commit();
    cp_wait1();
    __syncthreads();

    for (int kt = kt0; kt < kt_end; kt++) {
        const int slot = (kt - kt0) % 3;
        if (kt + 2 < kt_end) stage(kt + 2, (kt + 2 - kt0) % 3);
        else cp_commit();

        const uint32_t abase = s_addr + (uint32_t)slot * BUFW * 4
                             + (uint32_t)((warp_m * 64 + rowA) * PADW * 4 + kAb);
        const uint32_t bbase = s_addr + (uint32_t)(slot * BUFW + COMP) * 4
                             + (uint32_t)((warp_n * 32 + rowB) * PADW * 4 + kBb);

#pragma unroll
        for (int ks = 0; ks < 4; ks++) {
            const uint32_t koff = ks * 32;
            uint32_t a[4][4];
#pragma unroll
            for (int im = 0; im < 4; im++)
                ldsm_x4(a[im][0], a[im][1], a[im][2], a[im][3],
                        abase + im * (16 * PADW * 4) + koff);
            uint32_t bb[2][4];
#pragma unroll
            for (int p = 0; p < 2; p++)
                ldsm_x4(bb[p][0], bb[p][1], bb[p][2], bb[p][3],
                        bbase + p * (16 * PADW * 4) + koff);
#pragma unroll
            for (int im = 0; im < 4; im++)
#pragma unroll
                for (int in = 0; in < 4; in++)
                    mma_f16(acc[im][in], a[im], &bb[in >> 1][(in & 1) * 2]);
        }

        cp_wait1();
        __syncthreads();
    }

    // --- epilogue ---
    float* C0z = C0;
    if (EPI == 3)
        C0z = C0 + (size_t)blockIdx.z * TOKENS * 96;

#pragma unroll
    for (int im = 0; im < 4; im++) {
        const int r0 = block_row + warp_m * 64 + im * 16 + gr;
#pragma unroll
        for (int in = 0; in < 4; in++) {
            const int c0 = block_col + warp_n * 32 + in * 8 + 2 * tig;
#pragma unroll
            for (int half = 0; half < 2; half++) {
                const int r = r0 + half * 8;
                const float v0 = acc[im][in][2 * half];
                const float v1 = acc[im][in][2 * half + 1];
                if (EPI == 0) {
                    *reinterpret_cast<float2*>(&C0[(size_t)r * ldc + c0]) =
                        make_float2(v0, v1);
                } else if (EPI == 1) {
                    if (block_col < DIN_) {
                        *reinterpret_cast<__half2*>(&H0[(size_t)r * DIN_ + c0]) =
                            __floats2half2_rn(v0, v1);
                    } else {
                        const float s0 = v0 / (1.f + __expf(-v0));
                        const float s1 = v1 / (1.f + __expf(-v1));
                        *reinterpret_cast<__half2*>(
                            &H1[(size_t)r * DIN_ + (c0 - DIN_)]) =
                            __floats2half2_rn(s0, s1);
                    }
                } else if (EPI == 2) {
                    const float t0 = v0 + __ldg(&bias[c0]);
                    const float t1 = v1 + __ldg(&bias[c0 + 1]);
                    const float s0 = (t0 > 20.f) ? t0 : log1pf(__expf(t0));
                    const float s1 = (t1 > 20.f) ? t1 : log1pf(__expf(t1));
                    *reinterpret_cast<float2*>(&C0[(size_t)r * ldc + c0]) =
                        make_float2(s0, s1);
                } else { // EPI == 3
                    if (c0 + 1 < N) {
                        *reinterpret_cast<float2*>(&C0z[(size_t)r * ldc + c0]) =
                            make_float2(v0, v1);
                    } else if (c0 < N) {
                        C0z[(size_t)r * ldc + c0] = v0;
                    }
                }
            }
        }
    }
}

// ---------------------------------------------------------------------------
// Depthwise causal conv1d (k=4) + bias + SiLU; 8 ch/thread, fp16 in/out
// ---------------------------------------------------------------------------
__global__ void conv_silu_kernel(const __half* __restrict__ xs,
                                 const float* __restrict__ w,
                                 const float* __restrict__ bias,
                                 __half* __restrict__ uh)
{
    const int idx = blockIdx.x * blockDim.x + threadIdx.x;
    const int t = idx >> 8;
    const int c0 = (idx & 255) << 3;
    const int l = t & (L_ - 1);
    const int tbase = t - l;

    float acc[8];
    {
        const float4 b0 = *reinterpret_cast<const float4*>(&bias[c0]);
        const float4 b1 = *reinterpret_cast<const float4*>(&bias[c0 + 4]);
        acc[0] = b0.x; acc[1] = b0.y; acc[2] = b0.z; acc[3] = b0.w;
        acc[4] = b1.x; acc[5] = b1.y; acc[6] = b1.z; acc[7] = b1.w;
    }
    float wv[8][4];
#pragma unroll
    for (int j = 0; j < 8; j++) {
        const float4 w4 = *reinterpret_cast<const float4*>(&w[(c0 + j) * 4]);
        wv[j][0] = w4.x; wv[j][1] = w4.y; wv[j][2] = w4.z; wv[j][3] = w4.w;
    }

#pragma unroll
    for (int k = 0; k < 4; k++) {
        const int lp = l - 3 + k;
        if (lp >= 0) {
            const uint4 hv = *reinterpret_cast<const uint4*>(
                xs + ((size_t)(tbase + lp) * DIN_ + c0));
            const __half2* h2 = reinterpret_cast<const __half2*>(&hv);
#pragma unroll
            for (int p = 0; p < 4; p++) {
                const float2 f = __half22float2(h2[p]);
                acc[2 * p]     = fmaf(f.x, wv[2 * p][k],     acc[2 * p]);
                acc[2 * p + 1] = fmaf(f.y, wv[2 * p + 1][k], acc[2 * p + 1]);
            }
        }
    }

    __half2 hs[4];
#pragma unroll
    for (int p = 0; p < 4; p++) {
        const float a0 = acc[2 * p], a1 = acc[2 * p + 1];
        hs[p] = __floats2half2_rn(a0 / (1.f + __expf(-a0)),
                                  a1 / (1.f + __expf(-a1)));
    }
    *reinterpret_cast<uint4*>(uh + (size_t)t * DIN_ + c0) =
        *reinterpret_cast<uint4*>(hs);
}

// ---------------------------------------------------------------------------
// Segmented scan pass 1: per (b, seg, d, n) compute (prod dA, local h end)
// ---------------------------------------------------------------------------
__global__ void scan_pass1(const float* __restrict__ delta,
                           const __half* __restrict__ uh,
                           const float* __restrict__ xdbl,
                           const float* __restrict__ A_log,
                           float* __restrict__ segA,
                           float* __restrict__ segH)
{
    constexpr int CH = 64;
    __shared__ float sD[CH][16];
    __shared__ float sU[CH][16];
    __shared__ float sB[CH][16];

    const int bs = blockIdx.y;
    const int b = bs >> 3;
    const int seg = bs & 7;
    const int dbase = blockIdx.x * 16;
    const int tid = threadIdx.x;
    const int warp = tid >> 5;
    const int lane = tid & 31;
    const int half = lane >> 4;
    const int n = lane & 15;
    const int dl = (warp << 1) + half;
    const int d = dbase + dl;

    const float cA = -__expf(A_log[d * NSTATE + n]) * 1.44269504f;

    const int li = tid & 15;
    const int lrow = tid >> 4;
    const int l0 = seg * SEGLEN;

    float h = 0.f, aP = 1.f;

    for (int c0 = 0; c0 < SEGLEN; c0 += CH) {
#pragma unroll
        for (int p = 0; p < CH / 16; p++) {
            const int l = l0 + c0 + p * 16 + lrow;
            const size_t t = (size_t)b * L_ + l;
            sD[p * 16 + lrow][li] = delta[t * DIN_ + dbase + li];
            sU[p * 16 + lrow][li] = __half2float(uh[t * DIN_ + dbase + li]);
            sB[p * 16 + lrow][li] = xdbl[t * 96 + 64 + li];
        }
        __syncthreads();

        for (int i = 0; i < CH; i++) {
            const float dlt = sD[i][dl];
            const float uu  = sU[i][dl];
            const float bb  = sB[i][n];
            const float dA  = exp2f(dlt * cA);
            h = fmaf(dA, h, dlt * bb * uu);
            aP *= dA;
        }
        __syncthreads();
    }

    const size_t o = ((size_t)bs * DIN_ + d) * NSTATE + n;
    segA[o] = aP;
    segH[o] = h;
}

// ---------------------------------------------------------------------------
// Segment combine: serial prefix over NSEG per chain -> h_init per segment
// ---------------------------------------------------------------------------
__global__ void scan_combine(const float* __restrict__ segA,
                             const float* __restrict__ segH,
                             float* __restrict__ hInit)
{
    const int idx = blockIdx.x * blockDim.x + threadIdx.x;
    if (idx >= B_ * DIN_ * NSTATE) return;
    const int b = idx / (DIN_ * NSTATE);
    const int rem = idx - b * (DIN_ * NSTATE);
    float h = 0.f;
#pragma unroll
    for (int s = 0; s < NSEG; s++) {
        const size_t o = ((size_t)(b * NSEG + s) * DIN_) * NSTATE + rem;
        hInit[o] = h;
        h = segA[o] * h + segH[o];
    }
}

// ---------------------------------------------------------------------------
// Segmented scan pass 2: recompute recurrence from h_init, emit gated output
// ---------------------------------------------------------------------------
__global__ void scan_pass2(const float* __restrict__ delta,
                           const __half* __restrict__ uh,
                           const float* __restrict__ xdbl,
                           const __half* __restrict__ gateh,
                           const float* __restrict__ A_log,
                           const float* __restrict__ Dv,
                           const float* __restrict__ hInit,
                           __half* __restrict__ yh)
{
    constexpr int CH = 64;
    __shared__ float sD[CH][16];
    __shared__ float sU[CH][16];
    __shared__ float sG[CH][16];
    __shared__ float sB[CH][16];
    __shared__ float sC[CH][16];
    __shared__ float sY[CH][16];

    const int bs = blockIdx.y;
    const int b = bs >> 3;
    const int seg = bs & 7;
    const int dbase = blockIdx.x * 16;
    const int tid = threadIdx.x;
    const int warp = tid >> 5;
    const int lane = tid & 31;
    const int half = lane >> 4;
    const int n = lane & 15;
    const int dl = (warp << 1) + half;
    const int d = dbase + dl;

    const float cA = -__expf(A_log[d * NSTATE + n]) * 1.44269504f;
    const float Dd = Dv[d];

    const int li = tid & 15;
    const int lrow = tid >> 4;
    const int l0 = seg * SEGLEN;

    float h = hInit[((size_t)bs * DIN_ + d) * NSTATE + n];

    for (int c0 = 0; c0 < SEGLEN; c0 += CH) {
#pragma unroll
        for (int p = 0; p < CH / 16; p++) {
            const int l = l0 + c0 + p * 16 + lrow;
            const size_t t = (size_t)b * L_ + l;
            sD[p * 16 + lrow][li] = delta[t * DIN_ + dbase + li];
            sU[p * 16 + lrow][li] = __half2float(uh[t * DIN_ + dbase + li]);
            sG[p * 16 + lrow][li] = __half2float(gateh[t * DIN_ + dbase + li]);
            sB[p * 16 + lrow][li] = xdbl[t * 96 + 64 + li];
            sC[p * 16 + lrow][li] = xdbl[t * 96 + 80 + li];
        }
        __syncthreads();

        for (int i = 0; i < CH; i++) {
            const float dlt = sD[i][dl];
            const float uu  = sU[i][dl];
            const float bb  = sB[i][n];
            const float cc  = sC[i][n];
            const float dA  = exp2f(dlt * cA);
            h = fmaf(dA, h, dlt * bb * uu);
            float py = h * cc;
            py += __shfl_xor_sync(0xffffffffu, py, 1);
            py += __shfl_xor_sync(0xffffffffu, py, 2);
            py += __shfl_xor_sync(0xffffffffu, py, 4);
            py += __shfl_xor_sync(0xffffffffu, py, 8);
            if (n == 0)
                sY[i][dl] = (py + uu * Dd) * sG[i][dl];
        }
        __syncthreads();

#pragma unroll
        for (int p = 0; p < CH / 16; p++) {
            const int l = l0 + c0 + p * 16 + lrow;
            yh[((size_t)b * L_ + l) * DIN_ + dbase + li] =
                __float2half_rn(sY[p * 16 + lrow][li]);
        }
        __syncthreads();
    }
}

// ---------------------------------------------------------------------------
extern "C" void kernel_launch(void* const* d_in, const int* in_sizes, int n_in,
                              void* d_out, int out_size)
{
    const float* x      = (const float*)d_in[0];
    const float* W_in   = (const float*)d_in[1];
    const float* conv_w = (const float*)d_in[2];
    const float* conv_b = (const float*)d_in[3];
    const float* W_x    = (const float*)d_in[4];
    const float* W_dt   = (const float*)d_in[5];
    const float* b_dt   = (const float*)d_in[6];
    const float* W_out  = (const float*)d_in[7];
    const float* A_log  = (const float*)d_in[8];
    const float* Dv     = (const float*)d_in[9];
    float* out = (float*)d_out;

    float *xdbl, *xdbl_part, *delta, *segA, *segH, *hInit;
    __half *xh, *xsh, *gateh, *uh, *xdh, *yh, *win, *wx, *wdt, *wout;
    cudaGetSymbolAddress((void**)&xdbl,      g_xdbl);
    cudaGetSymbolAddress((void**)&xdbl_part, g_xdbl_part);
    cudaGetSymbolAddress((void**)&delta,     g_delta);
    cudaGetSymbolAddress((void**)&segA,      g_segA);
    cudaGetSymbolAddress((void**)&segH,      g_segH);
    cudaGetSymbolAddress((void**)&hInit,     g_hInit);
    cudaGetSymbolAddress((void**)&xh,        g_xh);
    cudaGetSymbolAddress((void**)&xsh,       g_xsh);
    cudaGetSymbolAddress((void**)&gateh,     g_gateh);
    cudaGetSymbolAddress((void**)&uh,        g_uh);
    cudaGetSymbolAddress((void**)&xdh,       g_xdh);
    cudaGetSymbolAddress((void**)&yh,        g_yh);
    cudaGetSymbolAddress((void**)&win,       g_win);
    cudaGetSymbolAddress((void**)&wx,        g_wx);
    cudaGetSymbolAddress((void**)&wdt,       g_wdt);
    cudaGetSymbolAddress((void**)&wout,     g_wout);

    constexpr int SMEM = 3 * 2 * 128 * 36 * 4;  // 110592 bytes (3-stage)
    cudaFuncSetAttribute(gemm_f16<0>, cudaFuncAttributeMaxDynamicSharedMemorySize, SMEM);
    cudaFuncSetAttribute(gemm_f16<1>, cudaFuncAttributeMaxDynamicSharedMemorySize, SMEM);
    cudaFuncSetAttribute(gemm_f16<2>, cudaFuncAttributeMaxDynamicSharedMemorySize, SMEM);
    cudaFuncSetAttribute(gemm_f16<3>, cudaFuncAttributeMaxDynamicSharedMemorySize, SMEM);

    // (G1 at launch index 3 so ncu capture lands on it)
    to_f16<<<(TOKENS * DIM_ + 255) / 256, 256>>>(x, xh, TOKENS * DIM_);
    transpose_f16<<<dim3(2 * DIN_ / 32, DIM_ / 32), dim3(32, 8)>>>(W_in, win, DIM_, 2 * DIN_);
    transpose_f16<<<dim3(96 / 32, DIN_ / 32), dim3(32, 8)>>>(W_x, wx, DIN_, 96);

    // G1: x @ W_in -> xs (fp16) / silu(res) (fp16 gate)
    gemm_f16<1><<<dim3(2 * DIN_ / 128, TOKENS / 128, 1), 256, SMEM>>>(
        xh, DIM_, win, DIM_, 2 * DIN_, DIM_, nullptr, nullptr, xsh, gateh, 0);

    transpose_f16<<<dim3(DIN_ / 32, DTR_ / 32), dim3(32, 8)>>>(W_dt, wdt, DTR_, DIN_);
    transpose_f16<<<dim3(DIM_ / 32, DIN_ / 32), dim3(32, 8)>>>(W_out, wout, DIN_, DIM_);

    // Depthwise causal conv + SiLU -> uh (fp16)
    conv_silu_kernel<<<TOKENS, 256>>>(xsh, conv_w, conv_b, uh);

    // G3: x_dbl = u @ W_x (N=96), deterministic split-K=8
    gemm_f16<3><<<dim3(1, TOKENS / 128, SPLITK), 256, SMEM>>>(
        uh, DIN_, wx, DIN_, 96, DIN_, nullptr, xdbl_part, nullptr, nullptr, 96);
    reduce_splitk<<<(TOKENS * 96 + 255) / 256, 256>>>(xdbl_part, xdbl, xdh);

    // G4: delta = softplus(x_dbl[:, :64] @ W_dt + b_dt)
    gemm_f16<2><<<dim3(DIN_ / 128, TOKENS / 128, 1), 256, SMEM>>>(
        xdh, 96, wdt, DTR_, DIN_, DTR_, b_dt, delta, nullptr, nullptr, DIN_);

    // Segmented selective scan: pass1 -> combine -> pass2
    scan_pass1<<<dim3(DIN_ / 16, B_ * NSEG), 256>>>(
        delta, uh, xdbl, A_log, segA, segH);
    scan_combine<<<(B_ * DIN_ * NSTATE + 255) / 256, 256>>>(
        segA, segH, hInit);
    scan_pass2<<<dim3(DIN_ / 16, B_ * NSEG), 256>>>(
        delta, uh, xdbl, gateh, A_log, Dv, hInit, yh);

    // G6: out = ys @ W_out
    gemm_f16<0><<<dim3(DIM_ / 128, TOKENS / 128, 1), 256, SMEM>>>(
        yh, DIN_, wout, DIN_, DIM_, DIN_, nullptr, out, nullptr, nullptr, DIM_);
}